// round 16
// baseline (speedup 1.0000x reference)
#include <cuda_runtime.h>
#include <cstdint>

#define BB  4
#define NN  16384
#define SS  4096
#define KK  32
#define CINF 16
#define C0  19
#define C1  32
#define C2  32
#define C3  64
#define EPSF 1e-5f

// spatial grid
#define GG     32
#define NC     (GG * GG * GG)
#define BOUNDF 4.5f
#define HH     (9.0f / (float)GG)
#define MARGIN 1e-3f

#define FINF __int_as_float(0x7f800000)

// ---------------- scratch (no allocs allowed) ----------------
__device__ int    g_knn[BB * SS * KK];
__device__ float  g_a1[C1], g_b1[C1];
__device__ float  g_a2[C2], g_b2[C2];
__device__ float  g_a3[C3], g_b3[C3];

__device__ float4 g_pts[BB * NN];        // cell-sorted (x, y, z, ||p||^2)
__device__ int    g_pidx[BB * NN];       // in-batch original index
__device__ int    g_cell[BB * NN];       // cell id per original point
__device__ int    g_cnt[BB * NC];
__device__ int    g_cstart[BB * NC + 1];
__device__ int    g_ccur[BB * NC];
__device__ int    g_bsum[BB * 32];
__device__ int    g_boff[BB * 32];

// ---------------- packed f32x2 helpers (bitwise == two scalar fma.rn) --------
__device__ __forceinline__ unsigned long long packf2(float v)
{
    unsigned long long r;
    asm("mov.b64 %0, {%1, %1};" : "=l"(r) : "f"(v));
    return r;
}
__device__ __forceinline__ void fma2(unsigned long long& a,
                                     unsigned long long x, unsigned long long w)
{
    asm("fma.rn.f32x2 %0, %1, %2, %0;" : "+l"(a) : "l"(x), "l"(w));
}
__device__ __forceinline__ void unpack2(unsigned long long a, float& lo, float& hi)
{
    asm("mov.b64 {%0, %1}, %2;" : "=f"(lo), "=f"(hi) : "l"(a));
}

// ---------------- prep: fold BN as post-affine ----------------
__global__ void prep_kernel(
    const float* __restrict__ b0,
    const float* __restrict__ g0, const float* __restrict__ bt0,
    const float* __restrict__ rm0, const float* __restrict__ rv0,
    const float* __restrict__ b1,
    const float* __restrict__ g1, const float* __restrict__ bt1,
    const float* __restrict__ rm1, const float* __restrict__ rv1,
    const float* __restrict__ b2,
    const float* __restrict__ g2, const float* __restrict__ bt2,
    const float* __restrict__ rm2, const float* __restrict__ rv2)
{
    int t = threadIdx.x;
    if (t < C1) {
        float A = g0[t] * rsqrtf(rv0[t] + EPSF);
        g_a1[t] = A;
        g_b1[t] = (b0[t] - rm0[t]) * A + bt0[t];
    }
    if (t < C2) {
        float A = g1[t] * rsqrtf(rv1[t] + EPSF);
        g_a2[t] = A;
        g_b2[t] = (b1[t] - rm1[t]) * A + bt1[t];
    }
    if (t < C3) {
        float A = g2[t] * rsqrtf(rv2[t] + EPSF);
        g_a3[t] = A;
        g_b3[t] = (b2[t] - rm2[t]) * A + bt2[t];
    }
}

// ---------------- binning ----------------
__global__ void zero_kernel()
{
    int i = blockIdx.x * blockDim.x + threadIdx.x;
    if (i < BB * NC) g_cnt[i] = 0;
}

__device__ __forceinline__ int clampi(int v) { return min(GG - 1, max(0, v)); }

__device__ __forceinline__ int cell_of(float x, float y, float z)
{
    int cx = clampi((int)floorf((x + BOUNDF) * (1.0f / HH)));
    int cy = clampi((int)floorf((y + BOUNDF) * (1.0f / HH)));
    int cz = clampi((int)floorf((z + BOUNDF) * (1.0f / HH)));
    return (cx * GG + cy) * GG + cz;
}

__global__ void count_kernel(const float* __restrict__ xyz)
{
    int i = blockIdx.x * blockDim.x + threadIdx.x;
    if (i >= BB * NN) return;
    int b = i >> 14;
    const float* p = xyz + (size_t)i * 3;
    int cell = cell_of(p[0], p[1], p[2]);
    g_cell[i] = cell;
    atomicAdd(&g_cnt[b * NC + cell], 1);
}

// hierarchical scan: (B) per-block scans, (C) scan of block sums, (D) add
__global__ void scanB_kernel()   // grid = BB*32, block = 1024, 1 cell/thread
{
    __shared__ int wsum[32];
    const unsigned FULL = 0xffffffffu;
    int t = threadIdx.x, lane = t & 31, w = t >> 5;
    int b = blockIdx.x >> 5, blk = blockIdx.x & 31;
    int cell = blk * 1024 + t;
    int cnt = g_cnt[b * NC + cell];
    int v = cnt;
#pragma unroll
    for (int o = 1; o < 32; o <<= 1) {
        int u = __shfl_up_sync(FULL, v, o);
        if (lane >= o) v += u;
    }
    if (lane == 31) wsum[w] = v;
    __syncthreads();
    if (w == 0) {
        int s = wsum[lane];
#pragma unroll
        for (int o = 1; o < 32; o <<= 1) {
            int u = __shfl_up_sync(FULL, s, o);
            if (lane >= o) s += u;
        }
        wsum[lane] = s;
    }
    __syncthreads();
    int excl = v - cnt + ((w > 0) ? wsum[w - 1] : 0);
    g_cstart[b * NC + cell] = excl;                 // block-local for now
    if (t == 1023) g_bsum[blockIdx.x] = excl + cnt; // block total
}

__global__ void scanC_kernel()   // 1 block, 128 threads; warp w = batch w
{
    const unsigned FULL = 0xffffffffu;
    int lane = threadIdx.x & 31, w = threadIdx.x >> 5;
    int v = g_bsum[w * 32 + lane];
    int inc = v;
#pragma unroll
    for (int o = 1; o < 32; o <<= 1) {
        int u = __shfl_up_sync(FULL, inc, o);
        if (lane >= o) inc += u;
    }
    g_boff[w * 32 + lane] = inc - v + w * NN;
}

__global__ void scanD_kernel()   // grid = BB*32, block = 1024
{
    int b = blockIdx.x >> 5, blk = blockIdx.x & 31;
    int cell = blk * 1024 + threadIdx.x;
    int off = g_boff[blockIdx.x];
    int i = b * NC + cell;
    int v = g_cstart[i] + off;
    g_cstart[i] = v;
    g_ccur[i] = v;
    if (blockIdx.x == 0 && threadIdx.x == 0) g_cstart[BB * NC] = BB * NN;
}

__global__ void scatter_kernel(const float* __restrict__ xyz)
{
    int i = blockIdx.x * blockDim.x + threadIdx.x;
    if (i >= BB * NN) return;
    int b = i >> 14;
    int cell = g_cell[i];
    int pos = atomicAdd(&g_ccur[b * NC + cell], 1);
    const float* p = xyz + (size_t)i * 3;
    float x = p[0], y = p[1], z = p[2];
    float pp = __fadd_rn(__fadd_rn(__fmul_rn(x, x), __fmul_rn(y, y)),
                         __fmul_rn(z, z));
    g_pts[pos] = make_float4(x, y, z, pp);
    g_pidx[pos] = i & (NN - 1);
}

// ---------------- binned KNN v5: pipelined chunks + cached bounds ------------
// Distances bitwise-identical to R5..R15 (validated):
//   qq, pp : (x*x + y*y) + z*z, mul+add, NO fma
//   dot2   : fma(2qz,pz, fma(2qy,py, rn(2qx*px))) == 2*dot bitwise
//   d      : (qq - dot2) + pp, NO fma
// Warp-distributed sorted top-32 of (d, idx); order-independent exact result.
__device__ __forceinline__ bool lessdi(float d1, int i1, float d2, int i2)
{
    return (d1 < d2) || (d1 == d2 && i1 < i2);
}

// full ascending bitonic sort of (d, ci) across 32 lanes (lex order)
__device__ __forceinline__ void bitonic32(float& d, int& ci, int lane)
{
    const unsigned FULL = 0xffffffffu;
#pragma unroll
    for (int k = 2; k <= 32; k <<= 1) {
#pragma unroll
        for (int j = k >> 1; j > 0; j >>= 1) {
            float d2 = __shfl_xor_sync(FULL, d, j);
            int   i2 = __shfl_xor_sync(FULL, ci, j);
            bool keepmin = (((lane & j) == 0) == ((lane & k) == 0));
            bool pless = lessdi(d2, i2, d, ci);
            if (keepmin == pless) { d = d2; ci = i2; }
        }
    }
}

// Candidate at flattened position g (binary search over the per-lane prefix
// table `off`, then g_pts load + distance). Independent of the top-K list.
__device__ __forceinline__ void cand_at(
    int g, bool valid, int off, int s0,
    float qx2, float qy2, float qz2, float qq,
    float& d, int& ci)
{
    const unsigned FULL = 0xffffffffu;
    int c = 0;
#pragma unroll
    for (int step = 16; step; step >>= 1) {
        int cand = c + step;
        int oc = __shfl_sync(FULL, off, cand);
        if (valid && oc <= g) c = cand;
    }
    int sc = __shfl_sync(FULL, s0, c);
    int oc = __shfl_sync(FULL, off, c);
    d = FINF;
    ci = 0x7fffffff;
    if (valid) {
        int jj = sc + (g - oc);
        float4 p = g_pts[jj];
        ci = g_pidx[jj];
        float dot2 = __fmaf_rn(qz2, p.z,
                     __fmaf_rn(qy2, p.y, __fmul_rn(qx2, p.x)));
        d = __fadd_rn(__fsub_rn(qq, dot2), p.w);
    }
}

// Scan a group of up to 32 per-lane segments [s0,e0), flattened so every
// chunk of 32 candidates fills all lanes. Chunk i+1's candidate is computed
// BEFORE merging chunk i (software pipeline) — identical candidate set and
// merge order, latency overlapped. virgin: first full chunk bitonic-sorts
// straight into the list; dense chunks use the exact merge network.
__device__ void scan_group_flat(
    int s0, int e0, int lane, float qx2, float qy2, float qz2, float qq,
    float& kd, float& ld, int& li, bool& virgin)
{
    const unsigned FULL = 0xffffffffu;
    int len = max(e0 - s0, 0);
    int off = len;
#pragma unroll
    for (int o = 1; o < 32; o <<= 1) {
        int u = __shfl_up_sync(FULL, off, o);
        if (lane >= o) off += u;
    }
    int total = __shfl_sync(FULL, off, 31);
    off -= len;                                    // exclusive prefix
    if (total == 0) return;

    float d0; int ci0;
    cand_at(lane, lane < total, off, s0, qx2, qy2, qz2, qq, d0, ci0);

    for (int g0 = 0; g0 < total; g0 += 32) {
        float d1; int ci1;
        bool more = (g0 + 32) < total;
        if (more)
            cand_at(g0 + 32 + lane, g0 + 32 + lane < total, off, s0,
                    qx2, qy2, qz2, qq, d1, ci1);

        if (virgin && (total - g0 >= 32)) {
            // bitonic sort the full chunk ascending -> becomes the list
            float d = d0; int ci = ci0;
            bitonic32(d, ci, lane);
            ld = d; li = ci;
            kd = __shfl_sync(FULL, ld, 31);
        } else {
            unsigned m = __ballot_sync(FULL, d0 <= kd);
            int cnt = __popc(m);
            if (cnt >= 6) {
                // exact merge: sort survivors (losers = +inf), pair against
                // the reversed list, then 5-stage bitonic clean.
                bool keep = d0 <= kd;
                float cd = keep ? d0 : FINF;
                int   cc = keep ? ci0 : 0x7fffffff;
                bitonic32(cd, cc, lane);
                float rd = __shfl_sync(FULL, cd, 31 - lane);
                int   ri = __shfl_sync(FULL, cc, 31 - lane);
                bool take = lessdi(rd, ri, ld, li);
                float nd = take ? rd : ld;
                int   ni = take ? ri : li;
#pragma unroll
                for (int j = 16; j > 0; j >>= 1) {
                    float d2 = __shfl_xor_sync(FULL, nd, j);
                    int   i2 = __shfl_xor_sync(FULL, ni, j);
                    bool keepmin = ((lane & j) == 0);
                    bool pless = lessdi(d2, i2, nd, ni);
                    if (keepmin == pless) { nd = d2; ni = i2; }
                }
                ld = nd; li = ni;
                kd = __shfl_sync(FULL, ld, 31);
            } else if (m) {
                do {
                    int src = __ffs(m) - 1;
                    m &= m - 1;
                    float cd = __shfl_sync(FULL, d0, src);
                    int   cc = __shfl_sync(FULL, ci0, src);
                    bool eb = lessdi(ld, li, cd, cc);
                    int pos = __popc(__ballot_sync(FULL, eb));
                    float sd = __shfl_up_sync(FULL, ld, 1);
                    int   si = __shfl_up_sync(FULL, li, 1);
                    if (lane == pos)      { ld = cd; li = cc; }
                    else if (lane > pos)  { ld = sd; li = si; }
                } while (m);
                kd = __shfl_sync(FULL, ld, 31);
            }
        }
        virgin = false;
        d0 = d1; ci0 = ci1;
    }
}

__global__ void __launch_bounds__(256)
knn_kernel(const float* __restrict__ xyz, const int* __restrict__ sidx,
           float* __restrict__ out)
{
    const unsigned FULL = 0xffffffffu;
    int warp = threadIdx.x >> 5;
    int lane = threadIdx.x & 31;
    int qid = blockIdx.x * 8 + warp;
    int b = qid >> 12;

    int sid = sidx[qid];
    const float* qp = xyz + ((size_t)b * NN + sid) * 3;
    float x = qp[0], y = qp[1], z = qp[2];
    float qq = __fadd_rn(__fadd_rn(__fmul_rn(x, x), __fmul_rn(y, y)),
                         __fmul_rn(z, z));
    float qx2 = 2.0f * x, qy2 = 2.0f * y, qz2 = 2.0f * z;

    if (lane == 0) {                                // fold meta outputs
        out[qid * 3 + 0] = x;
        out[qid * 3 + 1] = y;
        out[qid * 3 + 2] = z;
        out[(size_t)BB * SS * 3 + (size_t)BB * SS * C3 + qid] = (float)sid;
    }

    int cx = clampi((int)floorf((x + BOUNDF) * (1.0f / HH)));
    int cy = clampi((int)floorf((y + BOUNDF) * (1.0f / HH)));
    int cz = clampi((int)floorf((z + BOUNDF) * (1.0f / HH)));
    int cbase = b * NC;

    // ---- Phase A: pick starting radius (box count >= 48 or box = grid) ----
    // Keeps the last radius's first-group (s,e) in registers so Phase B can
    // skip one dependent L2 round (values identical by construction).
    int r = 1;
    int sA = 0, eA = 0;
    for (;; r++) {
        bool full = (cx - r <= 0) && (cx + r >= GG - 1) &&
                    (cy - r <= 0) && (cy + r >= GG - 1) &&
                    (cz - r <= 0) && (cz + r >= GG - 1);
        int n = 2 * r + 1, nxy = n * n;
        int zlo = max(cz - r, 0), zhi = min(cz + r, GG - 1);
        int total = 0;
        for (int basec = 0; basec < nxy; basec += 32) {
            int idx = basec + lane;
            int s = 0, e = 0;
            if (idx < nxy) {
                int xx = cx + idx / n - r, yy = cy + idx % n - r;
                if (xx >= 0 && xx < GG && yy >= 0 && yy < GG) {
                    int cid = cbase + (xx * GG + yy) * GG;
                    s = g_cstart[cid + zlo];
                    e = g_cstart[cid + zhi + 1];
                }
            }
            if (basec == 0) { sA = s; eA = e; }
            int cnt = e - s;
#pragma unroll
            for (int o = 16; o; o >>= 1) cnt += __shfl_xor_sync(FULL, cnt, o);
            total += cnt;
        }
        if (total >= 48 || full) break;
    }

    float ld = FINF;
    int   li = 0x7fffffff;
    float kd = ld;
    bool  virgin = true;

    // ---- Phase B: flattened scan of the radius-r box ----
    {
        int n = 2 * r + 1, nxy = n * n;
        int zlo = max(cz - r, 0), zhi = min(cz + r, GG - 1);
        for (int basec = 0; basec < nxy; basec += 32) {
            int s0, e0;
            if (basec == 0) { s0 = sA; e0 = eA; }   // cached from Phase A
            else {
                s0 = 0; e0 = 0;
                int idx = basec + lane;
                if (idx < nxy) {
                    int xx = cx + idx / n - r, yy = cy + idx % n - r;
                    if (xx >= 0 && xx < GG && yy >= 0 && yy < GG) {
                        int cid = cbase + (xx * GG + yy) * GG;
                        s0 = g_cstart[cid + zlo];
                        e0 = g_cstart[cid + zhi + 1];
                    }
                }
            }
            scan_group_flat(s0, e0, lane, qx2, qy2, qz2, qq, kd, ld, li, virgin);
        }
    }

    // ---- expand shells until safety bound holds ----
    for (;;) {
        bool full = (cx - r <= 0) && (cx + r >= GG - 1) &&
                    (cy - r <= 0) && (cy + r >= GG - 1) &&
                    (cz - r <= 0) && (cz + r >= GG - 1);
        float rb = (float)r * HH;
        if (full || kd < rb * rb - MARGIN) break;
        r++;
        int n = 2 * r + 1, nxy = n * n;
        int zlo = max(cz - r, 0), zhi = min(cz + r, GG - 1);
        for (int basec = 0; basec < nxy; basec += 32) {
            int idx = basec + lane;
            int s1 = 0, e1 = 0, s2 = 0, e2 = 0;
            if (idx < nxy) {
                int dx = idx / n - r, dy = idx % n - r;
                int xx = cx + dx, yy = cy + dy;
                if (xx >= 0 && xx < GG && yy >= 0 && yy < GG) {
                    int cid = cbase + (xx * GG + yy) * GG;
                    int adx = (dx < 0) ? -dx : dx, ady = (dy < 0) ? -dy : dy;
                    if (adx == r || ady == r) {          // new perimeter column
                        s1 = g_cstart[cid + zlo];
                        e1 = g_cstart[cid + zhi + 1];
                    } else {                              // two new z cells
                        int z1 = cz - r;
                        if (z1 >= 0) { s1 = g_cstart[cid + z1]; e1 = g_cstart[cid + z1 + 1]; }
                        int z2 = cz + r;
                        if (z2 < GG) { s2 = g_cstart[cid + z2]; e2 = g_cstart[cid + z2 + 1]; }
                    }
                }
            }
            scan_group_flat(s1, e1, lane, qx2, qy2, qz2, qq, kd, ld, li, virgin);
            scan_group_flat(s2, e2, lane, qx2, qy2, qz2, qq, kd, ld, li, virgin);
        }
    }

    g_knn[(size_t)qid * KK + lane] = li;
}

// ---------------- distributed warp max-reduce stage ----------------
template <int M, int SH>
__device__ __forceinline__ void redstage(float* o, int l)
{
    int bit = (l >> SH) & 1;
#pragma unroll
    for (int i = 0; i < M; i++) {
        float snd = bit ? o[i] : o[M + i];
        float rcv = __shfl_xor_sync(0xffffffffu, snd, 1 << SH);
        float mine = bit ? o[M + i] : o[i];
        o[i] = fmaxf(mine, rcv);
    }
}

// ---------------- MLP + maxpool (unchanged from R14/R15) ----------------
__global__ void __launch_bounds__(256, 3)
mlp_kernel(const float* __restrict__ xyz, const float* __restrict__ feat,
           const int* __restrict__ sidx,
           const float* __restrict__ w1g, const float* __restrict__ w2g,
           const float* __restrict__ w3g,
           float* __restrict__ out)
{
    __shared__ __align__(16) float sW1[C0 * C1];
    __shared__ __align__(16) float sW2[C1 * C2];
    __shared__ __align__(16) float sW3[C2 * C3];
    __shared__ float sA1[C1], sB1[C1], sA2[C2], sB2[C2], sA3[C3], sB3[C3];
    for (int i = threadIdx.x; i < C0 * C1; i += 256) sW1[i] = w1g[i];
    for (int i = threadIdx.x; i < C1 * C2; i += 256) sW2[i] = w2g[i];
    for (int i = threadIdx.x; i < C2 * C3; i += 256) sW3[i] = w3g[i];
    if (threadIdx.x < C1) { sA1[threadIdx.x] = g_a1[threadIdx.x]; sB1[threadIdx.x] = g_b1[threadIdx.x]; }
    if (threadIdx.x < C2) { sA2[threadIdx.x] = g_a2[threadIdx.x]; sB2[threadIdx.x] = g_b2[threadIdx.x]; }
    if (threadIdx.x < C3) { sA3[threadIdx.x] = g_a3[threadIdx.x]; sB3[threadIdx.x] = g_b3[threadIdx.x]; }
    __syncthreads();

    int warp = threadIdx.x >> 5;
    int lane = threadIdx.x & 31;
    int qid = blockIdx.x * 8 + warp;
    int b = qid >> 12;

    int sid = sidx[qid];
    const float* qp = xyz + ((size_t)b * NN + sid) * 3;
    float qx = qp[0], qy = qp[1], qz = qp[2];

    int nb = g_knn[(size_t)qid * KK + lane];
    const float* pp = xyz + ((size_t)b * NN + nb) * 3;

    float x[C0];
    x[0] = pp[0] - qx;
    x[1] = pp[1] - qy;
    x[2] = pp[2] - qz;
    const float4* f4 = (const float4*)(feat + ((size_t)b * NN + nb) * CINF);
#pragma unroll
    for (int v = 0; v < 4; v++) {
        float4 fv = f4[v];
        x[3 + 4 * v] = fv.x; x[4 + 4 * v] = fv.y;
        x[5 + 4 * v] = fv.z; x[6 + 4 * v] = fv.w;
    }

    // layer 1: 19 -> 32 (single pass, 16 packed accumulators)
    float y[C1];
    {
        unsigned long long a1[C1 / 2];
#pragma unroll
        for (int j = 0; j < C1 / 2; j++) a1[j] = 0ull;
        const ulonglong2* Wv = (const ulonglong2*)sW1;
#pragma unroll
        for (int c = 0; c < C0; c++) {
            unsigned long long xp = packf2(x[c]);
#pragma unroll
            for (int q = 0; q < C1 / 4; q++) {
                ulonglong2 wv = Wv[c * (C1 / 4) + q];
                fma2(a1[2 * q + 0], xp, wv.x);
                fma2(a1[2 * q + 1], xp, wv.y);
            }
        }
#pragma unroll
        for (int j = 0; j < C1 / 2; j++) unpack2(a1[j], y[2 * j], y[2 * j + 1]);
    }
#pragma unroll
    for (int d = 0; d < C1; d++)
        y[d] = fmaxf(fmaf(y[d], sA1[d], sB1[d]), 0.0f);

    // layer 2: 32 -> 32 (single pass)
    float z[C2];
    {
        unsigned long long a2[C2 / 2];
#pragma unroll
        for (int j = 0; j < C2 / 2; j++) a2[j] = 0ull;
        const ulonglong2* Wv = (const ulonglong2*)sW2;
#pragma unroll
        for (int c = 0; c < C1; c++) {
            unsigned long long xp = packf2(y[c]);
#pragma unroll
            for (int q = 0; q < C2 / 4; q++) {
                ulonglong2 wv = Wv[c * (C2 / 4) + q];
                fma2(a2[2 * q + 0], xp, wv.x);
                fma2(a2[2 * q + 1], xp, wv.y);
            }
        }
#pragma unroll
        for (int j = 0; j < C2 / 2; j++) unpack2(a2[j], z[2 * j], z[2 * j + 1]);
    }
#pragma unroll
    for (int d = 0; d < C2; d++)
        z[d] = fmaxf(fmaf(z[d], sA2[d], sB2[d]), 0.0f);

    // layer 3: 32 -> 64 in two 32-channel halves, each pooled immediately.
    const ulonglong2* Wv3 = (const ulonglong2*)sW3;   // 16 ulonglong2 per row
    int chb = (((lane >> 0) & 1) << 4) | (((lane >> 1) & 1) << 3) |
              (((lane >> 2) & 1) << 2) | (((lane >> 3) & 1) << 1) |
              (((lane >> 4) & 1) << 0);
    float* obase = out + (size_t)BB * SS * 3 + (size_t)qid * C3;
#pragma unroll
    for (int half = 0; half < 2; half++) {
        float oh[32];
        {
            unsigned long long a3[16];
#pragma unroll
            for (int j = 0; j < 16; j++) a3[j] = 0ull;
#pragma unroll
            for (int c = 0; c < C2; c++) {
                unsigned long long xp = packf2(z[c]);
#pragma unroll
                for (int q = 0; q < 8; q++) {
                    ulonglong2 wv = Wv3[c * 16 + half * 8 + q];
                    fma2(a3[2 * q + 0], xp, wv.x);
                    fma2(a3[2 * q + 1], xp, wv.y);
                }
            }
#pragma unroll
            for (int j = 0; j < 16; j++) unpack2(a3[j], oh[2 * j], oh[2 * j + 1]);
        }
#pragma unroll
        for (int d = 0; d < 32; d++) {
            int dc = half * 32 + d;
            oh[d] = fmaxf(fmaf(oh[d], sA3[dc], sB3[dc]), 0.0f);
        }
        // pool this half: 32 channels -> 1 channel per lane
        redstage<16, 0>(oh, lane);
        redstage<8,  1>(oh, lane);
        redstage<4,  2>(oh, lane);
        redstage<2,  3>(oh, lane);
        redstage<1,  4>(oh, lane);
        obase[half * 32 + chb] = oh[0];
    }
}

// ---------------- launch ----------------
extern "C" void kernel_launch(void* const* d_in, const int* in_sizes, int n_in,
                              void* d_out, int out_size)
{
    const float* xyz     = (const float*)d_in[0];
    const float* feature = (const float*)d_in[1];
    const int*   sidx    = (const int*)d_in[2];

    const float* w0  = (const float*)d_in[3];
    const float* b0  = (const float*)d_in[4];
    const float* g0  = (const float*)d_in[5];
    const float* bt0 = (const float*)d_in[6];
    const float* rm0 = (const float*)d_in[7];
    const float* rv0 = (const float*)d_in[8];
    const float* w1  = (const float*)d_in[9];
    const float* b1  = (const float*)d_in[10];
    const float* g1  = (const float*)d_in[11];
    const float* bt1 = (const float*)d_in[12];
    const float* rm1 = (const float*)d_in[13];
    const float* rv1 = (const float*)d_in[14];
    const float* w2  = (const float*)d_in[15];
    const float* b2  = (const float*)d_in[16];
    const float* g2  = (const float*)d_in[17];
    const float* bt2 = (const float*)d_in[18];
    const float* rm2 = (const float*)d_in[19];
    const float* rv2 = (const float*)d_in[20];

    float* out = (float*)d_out;

    prep_kernel<<<1, 256>>>(b0, g0, bt0, rm0, rv0,
                            b1, g1, bt1, rm1, rv1,
                            b2, g2, bt2, rm2, rv2);
    zero_kernel<<<(BB * NC + 255) / 256, 256>>>();
    count_kernel<<<(BB * NN + 255) / 256, 256>>>(xyz);
    scanB_kernel<<<BB * 32, 1024>>>();
    scanC_kernel<<<1, 128>>>();
    scanD_kernel<<<BB * 32, 1024>>>();
    scatter_kernel<<<(BB * NN + 255) / 256, 256>>>(xyz);
    knn_kernel<<<(BB * SS) / 8, 256>>>(xyz, sidx, out);
    mlp_kernel<<<(BB * SS) / 8, 256>>>(xyz, feature, sidx, w0, w1, w2, out);
}